// round 5
// baseline (speedup 1.0000x reference)
#include <cuda_runtime.h>
#include <math.h>

// Problem constants (fixed instance)
#define B_   2
#define L_   8192
#define G_   256
#define DG_  8
#define D_   2048          // G_*DG_
#define M_   8192          // complex FFT length (= L)
#define HFS_ 8208          // Hf row stride (>= 8193, 16B-multiple)

// -------- device scratch (static: no runtime allocation allowed) ----------
__device__ float  g_kvt[(size_t)B_ * D_ * L_];   // (B, D, L) kv, then y in place
__device__ float2 g_Hf[(size_t)G_ * HFS_];       // rfft(h_g) bins 0..8192
__device__ float2 g_tw[M_];                      // e^{-2*pi*i*k/16384}, k<8192

// smem bank swizzle: injects bits 4..7 into the bank field (bits 0..3).
// Makes both unit-stride and power-of-2-strided float2 access 2-phase (minimal).
__device__ __forceinline__ int sw(int c){ return c ^ ((c >> 4) & 0xF); }

// -------- complex helpers --------------------------------------------------
__device__ __forceinline__ float2 cadd(float2 a, float2 b){ return make_float2(a.x+b.x, a.y+b.y); }
__device__ __forceinline__ float2 csub(float2 a, float2 b){ return make_float2(a.x-b.x, a.y-b.y); }
__device__ __forceinline__ float2 cmul(float2 a, float2 b){
    return make_float2(a.x*b.x - a.y*b.y, a.x*b.y + a.y*b.x);
}
// multiply by DIR*i  (DIR=-1: -i*z ; DIR=+1: +i*z)
template<int DIR>
__device__ __forceinline__ float2 jmul(float2 z){
    return (DIR < 0) ? make_float2(z.y, -z.x) : make_float2(-z.y, z.x);
}

// -------- 8-point DFT (kernel e^{DIR*2*pi*i*r*j/8}) ------------------------
template<int DIR>
__device__ __forceinline__ void dft8(const float2 a[8], float2 B[8]){
    const float C = 0.70710678118654752f;
    float2 s0 = cadd(a[0], a[4]), s1 = csub(a[0], a[4]);
    float2 s2 = cadd(a[2], a[6]), s3 = csub(a[2], a[6]);
    float2 e0 = cadd(s0, s2),     e2 = csub(s0, s2);
    float2 js3 = jmul<DIR>(s3);
    float2 e1 = cadd(s1, js3),    e3 = csub(s1, js3);
    float2 u0 = cadd(a[1], a[5]), u1 = csub(a[1], a[5]);
    float2 u2 = cadd(a[3], a[7]), u3 = csub(a[3], a[7]);
    float2 o0 = cadd(u0, u2),     o2 = csub(u0, u2);
    float2 ju3 = jmul<DIR>(u3);
    float2 o1 = cadd(u1, ju3),    o3 = csub(u1, ju3);
    const float2 w1 = make_float2( C, (DIR < 0) ? -C : C);
    const float2 w3 = make_float2(-C, (DIR < 0) ? -C : C);
    float2 t1 = cmul(w1, o1);
    float2 t2 = jmul<DIR>(o2);
    float2 t3 = cmul(w3, o3);
    B[0] = cadd(e0, o0); B[4] = csub(e0, o0);
    B[1] = cadd(e1, t1); B[5] = csub(e1, t1);
    B[2] = cadd(e2, t2); B[6] = csub(e2, t2);
    B[3] = cadd(e3, t3); B[7] = csub(e3, t3);
}

// -------- one radix-8 Stockham pass (x -> y), s = 1<<LS ---------------------
// FIRST: input is zero for indices >= 4096 (skip those shared reads)
template<int DIR, int LS, bool FIRST>
__device__ __forceinline__ void pass_r8(const float2* __restrict__ x,
                                        float2* __restrict__ y){
    const int s = 1 << LS;
    for (int t = threadIdx.x; t < 1024; t += blockDim.x){
        const int q = t & (s - 1);
        const int p = t >> LS;
        float2 a[8];
        #pragma unroll
        for (int j = 0; j < 8; j++){
            if (FIRST && j >= 4) a[j] = make_float2(0.f, 0.f);
            else                 a[j] = x[sw(t + 1024 * j)];
        }
        float2 Bv[8];
        dft8<DIR>(a, Bv);
        float2 w1 = g_tw[p << (LS + 1)];
        if (DIR > 0) w1.y = -w1.y;
        float2 c[8];
        c[0] = Bv[0];
        float2 w = w1;
        #pragma unroll
        for (int r = 1; r < 8; r++){
            c[r] = cmul(w, Bv[r]);
            if (r < 7) w = cmul(w, w1);
        }
        const int base = q + (p << (LS + 3));
        #pragma unroll
        for (int r = 0; r < 8; r++)
            y[sw(base + (r << LS))] = c[r];
    }
}

// -------- final radix-16 pass: s = 512, p = 0 -> unit twiddles --------------
template<int DIR>
__device__ __forceinline__ void pass_r16(const float2* __restrict__ x,
                                         float2* __restrict__ y){
    const float C  = 0.70710678118654752f;
    const float c1 = 0.92387953251128676f;
    const float s1 = 0.38268343236508977f;
    const float wr[8] = {1.f,  c1,  C,  s1, 0.f, -s1, -C, -c1};
    const float wis[8] = {0.f, -s1, -C, -c1, -1.f, -c1, -C, -s1};
    for (int t = threadIdx.x; t < 512; t += blockDim.x){
        float2 ein[8];
        #pragma unroll
        for (int j = 0; j < 8; j++) ein[j] = x[sw(t + 1024 * j)];        // even p = 2j
        float2 E[8];
        dft8<DIR>(ein, E);
        float2 oin[8];
        #pragma unroll
        for (int j = 0; j < 8; j++) oin[j] = x[sw(t + 512 + 1024 * j)];  // odd p = 2j+1
        float2 O[8];
        dft8<DIR>(oin, O);
        #pragma unroll
        for (int k = 0; k < 8; k++){
            float wi = (DIR < 0) ? wis[k] : -wis[k];
            float2 tt = make_float2(wr[k]*O[k].x - wi*O[k].y,
                                    wr[k]*O[k].y + wi*O[k].x);
            y[sw(t + (k << 9))]         = cadd(E[k], tt);
            y[sw(t + ((k + 8) << 9))]   = csub(E[k], tt);
        }
    }
}

// 8192-point complex FFT (8*8*8*16). Input in a, RESULT lands back in a.
template<int DIR, bool FIRST_ZERO>
__device__ __forceinline__ void fft8192(float2* a, float2* b){
    pass_r8<DIR, 0, FIRST_ZERO>(a, b); __syncthreads();
    pass_r8<DIR, 3, false>(b, a);      __syncthreads();
    pass_r8<DIR, 6, false>(a, b);      __syncthreads();
    pass_r16<DIR>(b, a);               __syncthreads();
}

// -------- twiddle table ----------------------------------------------------
__global__ void tw_kernel(){
    int k = blockIdx.x * 256 + threadIdx.x;
    if (k < M_){
        double s, c;
        sincospi(-(double)k / 8192.0, &s, &c);   // angle = -2*pi*k/16384
        g_tw[k] = make_float2((float)c, (float)s);
    }
}

// -------- Hf = rfft(h_g, 16384), bins 0..8192 ------------------------------
__global__ void __launch_bounds__(1024) hf_kernel(const float* __restrict__ h){
    extern __shared__ float2 sm[];
    float2* a = sm;
    float2* b = sm + M_;
    const int g = blockIdx.x;
    const float2* h2 = reinterpret_cast<const float2*>(h + (size_t)g * L_);
    for (int i = threadIdx.x; i < 4096; i += blockDim.x) a[sw(i)] = h2[i];
    __syncthreads();
    fft8192<-1, true>(a, b);             // Z in a
    float2* Hf = g_Hf + (size_t)g * HFS_;
    for (int k = threadIdx.x; k <= 4096; k += blockDim.x){
        if (k == 0){
            float2 Z0 = a[sw(0)];
            Hf[0]    = make_float2(Z0.x + Z0.y, 0.f);
            Hf[8192] = make_float2(Z0.x - Z0.y, 0.f);
        } else if (k == 4096){
            float2 Z = a[sw(4096)];
            Hf[4096] = make_float2(Z.x, -Z.y);
        } else {
            float2 Zk = a[sw(k)], Zm = a[sw(8192 - k)];
            float2 Ze = make_float2(0.5f*(Zk.x + Zm.x), 0.5f*(Zk.y - Zm.y));
            float2 Zo = make_float2(0.5f*(Zk.y + Zm.y), -0.5f*(Zk.x - Zm.x));
            float2 WZo = cmul(g_tw[k], Zo);
            Hf[k] = cadd(Ze, WZo);
            float2 Xm = csub(Ze, WZo);
            Xm.y = -Xm.y;                 // conj
            Hf[8192 - k] = Xm;
        }
    }
}

// -------- pregate + transpose: kv_t(b,d,l) = x2(b,l,d)*v(b,l,d) ------------
__global__ void pregate_transpose(const float* __restrict__ x2,
                                  const float* __restrict__ v){
    __shared__ float tile[32][33];
    const int b  = blockIdx.z;
    const int l0 = blockIdx.x * 32;
    const int d0 = blockIdx.y * 32;
    #pragma unroll
    for (int i = 0; i < 32; i += 8){
        int l = l0 + threadIdx.y + i;
        size_t idx = ((size_t)b * L_ + l) * D_ + d0 + threadIdx.x;
        tile[threadIdx.y + i][threadIdx.x] = x2[idx] * v[idx];
    }
    __syncthreads();
    #pragma unroll
    for (int i = 0; i < 32; i += 8){
        int d = d0 + threadIdx.y + i;
        g_kvt[((size_t)b * D_ + d) * L_ + l0 + threadIdx.x] = tile[threadIdx.x][threadIdx.y + i];
    }
}

// -------- per-channel FFT convolution (in place in g_kvt) ------------------
__global__ void __launch_bounds__(1024) conv_kernel(const float* __restrict__ bias){
    extern __shared__ float2 sm[];
    float2* a = sm;
    float2* b = sm + M_;
    const int c = blockIdx.x;                 // c = bidx*D + d
    const int d = c & (D_ - 1);
    const int g = d >> 3;                     // DG_ = 8
    const float2* kv2 = reinterpret_cast<const float2*>(g_kvt + (size_t)c * L_);

    // pack: z[n] = kv[2n] + i*kv[2n+1], n<4096 ; upper half implicit zero
    for (int i = threadIdx.x; i < 4096; i += blockDim.x) a[sw(i)] = kv2[i];
    __syncthreads();

    fft8192<-1, true>(a, b);                  // Z in a (natural order)

    // Hermitian unpack * (H + bias) * repack — fully IN PLACE in a:
    // thread handling k touches exactly {k, 8192-k}, read-then-write, no race.
    const float bs = __ldg(bias + d);
    const float2* Hf = g_Hf + (size_t)g * HFS_;
    for (int k = threadIdx.x; k <= 4096; k += blockDim.x){
        if (k == 0){
            float2 Z0 = a[sw(0)];
            float X0 = Z0.x + Z0.y;
            float XM = Z0.x - Z0.y;
            float Y0 = X0 * (__ldg(&Hf[0].x)    + bs);
            float YM = XM * (__ldg(&Hf[8192].x) + bs);
            a[sw(0)] = make_float2(0.5f*(Y0 + YM), 0.5f*(Y0 - YM));
        } else if (k == 4096){
            float2 Z = a[sw(4096)];
            float2 X = make_float2(Z.x, -Z.y);
            float2 Gk = __ldg(&Hf[4096]); Gk.x += bs;
            float2 Y = cmul(X, Gk);
            a[sw(4096)] = make_float2(Y.x, -Y.y);
        } else {
            float2 Zk = a[sw(k)], Zm = a[sw(8192 - k)];
            float2 Ze = make_float2(0.5f*(Zk.x + Zm.x), 0.5f*(Zk.y - Zm.y));
            float2 Zo = make_float2(0.5f*(Zk.y + Zm.y), -0.5f*(Zk.x - Zm.x));
            float2 Wk = g_tw[k];
            float2 WZo = cmul(Wk, Zo);
            float2 Xk = cadd(Ze, WZo);
            float2 Xm = csub(Ze, WZo); Xm.y = -Xm.y;       // conj
            float2 Gk = __ldg(&Hf[k]);        Gk.x += bs;
            float2 Gm = __ldg(&Hf[8192 - k]); Gm.x += bs;
            float2 Yk = cmul(Xk, Gk);
            float2 Ym = cmul(Xm, Gm);
            float2 Ze2 = make_float2(0.5f*(Yk.x + Ym.x), 0.5f*(Yk.y - Ym.y));
            float2 T   = make_float2(0.5f*(Yk.x - Ym.x), 0.5f*(Yk.y + Ym.y));
            float2 Wc  = make_float2(Wk.x, -Wk.y);
            float2 Zo2 = cmul(Wc, T);
            a[sw(k)]        = make_float2(Ze2.x - Zo2.y,  Ze2.y + Zo2.x);
            a[sw(8192 - k)] = make_float2(Ze2.x + Zo2.y, -Ze2.y + Zo2.x);
        }
    }
    __syncthreads();

    fft8192<+1, false>(a, b);                 // result in a; y interleaved, scale 1/M

    float2* out2 = reinterpret_cast<float2*>(g_kvt + (size_t)c * L_);
    const float sc = 1.0f / 8192.0f;
    for (int i = threadIdx.x; i < 4096; i += blockDim.x){
        float2 z = a[sw(i)];
        out2[i] = make_float2(z.x * sc, z.y * sc);
    }
}

// -------- gate + transpose back: out(b,l,d) = x1(b,l,d) * y_t(b,d,l) -------
__global__ void gate_transpose(const float* __restrict__ x1,
                               float* __restrict__ out){
    __shared__ float tile[32][33];
    const int b  = blockIdx.z;
    const int l0 = blockIdx.x * 32;
    const int d0 = blockIdx.y * 32;
    #pragma unroll
    for (int i = 0; i < 32; i += 8){
        int d = d0 + threadIdx.y + i;
        tile[threadIdx.y + i][threadIdx.x] = g_kvt[((size_t)b * D_ + d) * L_ + l0 + threadIdx.x];
    }
    __syncthreads();
    #pragma unroll
    for (int i = 0; i < 32; i += 8){
        int l = l0 + threadIdx.y + i;
        size_t idx = ((size_t)b * L_ + l) * D_ + d0 + threadIdx.x;
        out[idx] = x1[idx] * tile[threadIdx.x][threadIdx.y + i];
    }
}

// ---------------------------------------------------------------------------
extern "C" void kernel_launch(void* const* d_in, const int* in_sizes, int n_in,
                              void* d_out, int out_size){
    const float* x1   = (const float*)d_in[0];
    const float* x2   = (const float*)d_in[1];
    const float* v    = (const float*)d_in[2];
    const float* h    = (const float*)d_in[3];
    const float* bias = (const float*)d_in[4];
    float* out = (float*)d_out;

    const int SMEM = 2 * M_ * (int)sizeof(float2);   // 131072 B
    cudaFuncSetAttribute(hf_kernel,   cudaFuncAttributeMaxDynamicSharedMemorySize, SMEM);
    cudaFuncSetAttribute(conv_kernel, cudaFuncAttributeMaxDynamicSharedMemorySize, SMEM);

    tw_kernel<<<(M_ + 255) / 256, 256>>>();
    hf_kernel<<<G_, 1024, SMEM>>>(h);

    dim3 tgrid(L_ / 32, D_ / 32, B_);
    dim3 tblk(32, 8);
    pregate_transpose<<<tgrid, tblk>>>(x2, v);

    conv_kernel<<<B_ * D_, 1024, SMEM>>>(bias);

    gate_transpose<<<tgrid, tblk>>>(x1, out);
}

// round 7
// speedup vs baseline: 1.0749x; 1.0749x over previous
#include <cuda_runtime.h>
#include <math.h>

// Problem constants (fixed instance)
#define B_   2
#define L_   8192
#define G_   256
#define DG_  8
#define D_   2048          // G_*DG_
#define M_   8192          // complex FFT length (= L)
#define HFS_ 8208          // Hf row stride (>= 8193, 16B-multiple)

// -------- device scratch (static: no runtime allocation allowed) ----------
__device__ __align__(256) float  g_kvt[(size_t)B_ * D_ * L_];  // (B,D,L) kv then y
__device__ __align__(256) float2 g_Hf[(size_t)G_ * HFS_];      // rfft(h_g) bins 0..8192
__device__ __align__(256) float2 g_tw[M_];                     // e^{-2*pi*i*k/16384}

// smem bank swizzle: inject bits 4..7 into the bank field (bits 0..3).
__device__ __forceinline__ int sw(int c){ return c ^ ((c >> 4) & 0xF); }

// -------- complex helpers --------------------------------------------------
__device__ __forceinline__ float2 cadd(float2 a, float2 b){ return make_float2(a.x+b.x, a.y+b.y); }
__device__ __forceinline__ float2 csub(float2 a, float2 b){ return make_float2(a.x-b.x, a.y-b.y); }
__device__ __forceinline__ float2 cmul(float2 a, float2 b){
    return make_float2(a.x*b.x - a.y*b.y, a.x*b.y + a.y*b.x);
}
template<int DIR>
__device__ __forceinline__ float2 jmul(float2 z){
    return (DIR < 0) ? make_float2(z.y, -z.x) : make_float2(-z.y, z.x);
}

// -------- 8-point DFT (kernel e^{DIR*2*pi*i*r*j/8}) ------------------------
template<int DIR>
__device__ __forceinline__ void dft8(const float2 a[8], float2 B[8]){
    const float C = 0.70710678118654752f;
    float2 s0 = cadd(a[0], a[4]), s1 = csub(a[0], a[4]);
    float2 s2 = cadd(a[2], a[6]), s3 = csub(a[2], a[6]);
    float2 e0 = cadd(s0, s2),     e2 = csub(s0, s2);
    float2 js3 = jmul<DIR>(s3);
    float2 e1 = cadd(s1, js3),    e3 = csub(s1, js3);
    float2 u0 = cadd(a[1], a[5]), u1 = csub(a[1], a[5]);
    float2 u2 = cadd(a[3], a[7]), u3 = csub(a[3], a[7]);
    float2 o0 = cadd(u0, u2),     o2 = csub(u0, u2);
    float2 ju3 = jmul<DIR>(u3);
    float2 o1 = cadd(u1, ju3),    o3 = csub(u1, ju3);
    const float2 w1 = make_float2( C, (DIR < 0) ? -C : C);
    const float2 w3 = make_float2(-C, (DIR < 0) ? -C : C);
    float2 t1 = cmul(w1, o1);
    float2 t2 = jmul<DIR>(o2);
    float2 t3 = cmul(w3, o3);
    B[0] = cadd(e0, o0); B[4] = csub(e0, o0);
    B[1] = cadd(e1, t1); B[5] = csub(e1, t1);
    B[2] = cadd(e2, t2); B[6] = csub(e2, t2);
    B[3] = cadd(e3, t3); B[7] = csub(e3, t3);
}

// log-depth twiddle powers: w[r] = w1^r
__device__ __forceinline__ void twpowers(float2 w1, float2 w[8]){
    w[1] = w1;
    w[2] = cmul(w1, w1);
    w[3] = cmul(w1, w[2]);
    w[4] = cmul(w[2], w[2]);
    w[5] = cmul(w[2], w[3]);
    w[6] = cmul(w[3], w[3]);
    w[7] = cmul(w[3], w[4]);
}

// -------- mid radix-8 Stockham pass (smem -> smem), s = 1<<LS --------------
// requires blockDim.x == 1024
template<int DIR, int LS>
__device__ __forceinline__ void pass_smem(const float2* __restrict__ x,
                                          float2* __restrict__ y){
    const int t  = threadIdx.x;
    const int q  = t & ((1 << LS) - 1);
    const int p  = t >> LS;
    const int xs = sw(t);                      // sw(t+1024j) = sw(t)+1024j (bits 4..7 fixed)
    float2 a[8];
    #pragma unroll
    for (int j = 0; j < 8; j++) a[j] = x[xs + 1024 * j];
    float2 Bv[8];
    dft8<DIR>(a, Bv);
    float2 w1 = g_tw[p << (LS + 1)];
    if (DIR > 0) w1.y = -w1.y;
    float2 w[8]; twpowers(w1, w);
    const int base = q + (p << (LS + 3));
    if constexpr (LS >= 8){
        // r<<LS occupies bits >= 9; disjoint from swizzle mask bits 4..7 & low nibble
        const int sb = sw(base);
        y[sb] = Bv[0];
        #pragma unroll
        for (int r = 1; r < 8; r++) y[sb + (r << LS)] = cmul(w[r], Bv[r]);
    } else {
        y[sw(base)] = Bv[0];
        #pragma unroll
        for (int r = 1; r < 8; r++) y[sw(base + (r << LS))] = cmul(w[r], Bv[r]);
    }
}

// -------- first forward pass: gmem -> smem, LS=0, upper half zero ----------
__device__ __forceinline__ void pass_first_gmem(const float2* __restrict__ g,
                                                float2* __restrict__ y){
    const int t = threadIdx.x;
    float2 a[8];
    #pragma unroll
    for (int j = 0; j < 4; j++) a[j] = __ldg(g + t + 1024 * j);
    #pragma unroll
    for (int j = 4; j < 8; j++) a[j] = make_float2(0.f, 0.f);
    float2 Bv[8];
    dft8<-1>(a, Bv);
    float2 w1 = g_tw[t << 1];
    float2 w[8]; twpowers(w1, w);
    // 8 consecutive outputs at base = t<<3; bits 4..7 constant across r<8,
    // so the swizzle mask m is constant but must be XORed per-index (not added).
    const int base = t << 3;
    const int m = (base >> 4) & 0xF;
    y[base ^ m] = Bv[0];
    #pragma unroll
    for (int r = 1; r < 8; r++) y[(base + r) ^ m] = cmul(w[r], Bv[r]);
}

// -------- last inverse pass: smem -> gmem, s=1024 => p=0 => unit twiddles --
// Only outputs n = t + 1024r < 4096 (r<4) are needed: y real signal keeps
// first 8192 reals = 4096 packed complex. Scale 1/8192 folded in.
__device__ __forceinline__ void pass_last_inv_gmem(const float2* __restrict__ x,
                                                   float2* __restrict__ g){
    const int t  = threadIdx.x;
    const int xs = sw(t);
    float2 a[8];
    #pragma unroll
    for (int j = 0; j < 8; j++) a[j] = x[xs + 1024 * j];
    float2 Bv[8];
    dft8<+1>(a, Bv);
    const float sc = 1.0f / 8192.0f;
    #pragma unroll
    for (int r = 0; r < 4; r++)
        g[t + 1024 * r] = make_float2(Bv[r].x * sc, Bv[r].y * sc);
}

// -------- Hermitian unpack/repack helpers (packed-real trick) ---------------
__device__ __forceinline__ void herm_unpack(float2 Zk, float2 Zm, float2 Wk,
                                            float2& Xk, float2& Xm){
    float2 Ze = make_float2(0.5f*(Zk.x + Zm.x), 0.5f*(Zk.y - Zm.y));
    float2 Zo = make_float2(0.5f*(Zk.y + Zm.y), -0.5f*(Zk.x - Zm.x));
    float2 WZo = cmul(Wk, Zo);
    Xk = cadd(Ze, WZo);
    Xm = csub(Ze, WZo); Xm.y = -Xm.y;          // conj
}
__device__ __forceinline__ void herm_repack(float2 Yk, float2 Ym, float2 Wk,
                                            float2& Ck, float2& Cm){
    float2 Ze2 = make_float2(0.5f*(Yk.x + Ym.x), 0.5f*(Yk.y - Ym.y));
    float2 T   = make_float2(0.5f*(Yk.x - Ym.x), 0.5f*(Yk.y + Ym.y));
    float2 Wc  = make_float2(Wk.x, -Wk.y);
    float2 Zo2 = cmul(Wc, T);
    Ck = make_float2(Ze2.x - Zo2.y,  Ze2.y + Zo2.x);
    Cm = make_float2(Ze2.x + Zo2.y, -Ze2.y + Zo2.x);
}

// -------- twiddle table ----------------------------------------------------
__global__ void tw_kernel(){
    int k = blockIdx.x * 256 + threadIdx.x;
    if (k < M_){
        double s, c;
        sincospi(-(double)k / 8192.0, &s, &c);   // -2*pi*k/16384
        g_tw[k] = make_float2((float)c, (float)s);
    }
}

// -------- Hf = rfft(h_g, 16384), bins 0..8192 ------------------------------
__global__ void __launch_bounds__(1024) hf_kernel(const float* __restrict__ h){
    extern __shared__ float2 sm[];
    float2* a = sm;
    float2* b = sm + M_;
    const int g = blockIdx.x;
    const float2* h2 = reinterpret_cast<const float2*>(h + (size_t)g * L_);

    pass_first_gmem(h2, a);     __syncthreads();
    pass_smem<-1, 3>(a, b);     __syncthreads();
    pass_smem<-1, 6>(b, a);     __syncthreads();
    pass_smem<-1, 9>(a, b);     __syncthreads();
    // b holds A ; Z[t] = A[t] + A[t+4096], Z[t+4096] = A[t] - A[t+4096]
    float2* Hf = g_Hf + (size_t)g * HFS_;
    for (int k = threadIdx.x; k < 2048; k += 1024){
        if (k == 0){
            float2 A0 = b[0],    A1 = b[4096];
            float2 A2 = b[2048], A3 = b[6144];   // sw() identity for these
            float2 Z0 = cadd(A0, A1), Z4 = csub(A0, A1);
            float2 Z2 = cadd(A2, A3), Z6 = csub(A2, A3);
            Hf[0]    = make_float2(Z0.x + Z0.y, 0.f);
            Hf[8192] = make_float2(Z0.x - Z0.y, 0.f);
            Hf[4096] = make_float2(Z4.x, -Z4.y);
            float2 Xk, Xm;
            herm_unpack(Z2, Z6, g_tw[2048], Xk, Xm);
            Hf[2048] = Xk; Hf[6144] = Xm;
        } else {
            const int k2 = 4096 - k;
            const int s1 = sw(k), s2 = sw(k2);   // sw(t+4096) = sw(t)+4096
            float2 A0 = b[s1], A1 = b[s1 + 4096];
            float2 A2 = b[s2], A3 = b[s2 + 4096];
            float2 Zk  = cadd(A0, A1);    // Z[k]
            float2 Zk4 = csub(A0, A1);    // Z[4096+k]
            float2 Zk2 = cadd(A2, A3);    // Z[4096-k]
            float2 Zm  = csub(A2, A3);    // Z[8192-k]
            float2 Xk, Xm, Xk2, Xk4;
            herm_unpack(Zk,  Zm,  g_tw[k],  Xk,  Xm);
            herm_unpack(Zk2, Zk4, g_tw[k2], Xk2, Xk4);
            Hf[k] = Xk;   Hf[8192 - k] = Xm;
            Hf[k2] = Xk2; Hf[4096 + k] = Xk4;
        }
    }
}

// -------- pregate + transpose: kv_t(b,d,l) = x2(b,l,d)*v(b,l,d) ------------
// block (8,32): tx covers 4 d's via float4, ty covers l (load) / d (store)
__global__ void pregate_transpose(const float* __restrict__ x2,
                                  const float* __restrict__ v){
    __shared__ float tile[32][33];               // [l-local][d-local]
    const int b  = blockIdx.z;
    const int l0 = blockIdx.x * 32;
    const int d0 = blockIdx.y * 32;
    const int tx = threadIdx.x;                  // 0..7
    const int ty = threadIdx.y;                  // 0..31
    {
        size_t idx = ((size_t)b * L_ + (l0 + ty)) * D_ + d0 + 4 * tx;
        float4 xa = *reinterpret_cast<const float4*>(x2 + idx);
        float4 va = *reinterpret_cast<const float4*>(v  + idx);
        tile[ty][4*tx + 0] = xa.x * va.x;
        tile[ty][4*tx + 1] = xa.y * va.y;
        tile[ty][4*tx + 2] = xa.z * va.z;
        tile[ty][4*tx + 3] = xa.w * va.w;
    }
    __syncthreads();
    {
        float4 o;
        o.x = tile[4*tx + 0][ty];
        o.y = tile[4*tx + 1][ty];
        o.z = tile[4*tx + 2][ty];
        o.w = tile[4*tx + 3][ty];
        *reinterpret_cast<float4*>(g_kvt + ((size_t)b * D_ + d0 + ty) * L_ + l0 + 4 * tx) = o;
    }
}

// -------- per-channel FFT convolution --------------------------------------
__global__ void __launch_bounds__(1024) conv_kernel(const float* __restrict__ bias){
    extern __shared__ float2 sm[];
    float2* a = sm;
    float2* b = sm + M_;
    const int c = blockIdx.x;                 // c = bidx*D + d
    const int d = c & (D_ - 1);
    const int g = d >> 3;                     // DG_ = 8
    const float2* kv2 = reinterpret_cast<const float2*>(g_kvt + (size_t)c * L_);

    // forward: gmem -> 4 radix-8 passes (trailing radix-2 folded into spectral)
    pass_first_gmem(kv2, a);    __syncthreads();
    pass_smem<-1, 3>(a, b);     __syncthreads();
    pass_smem<-1, 6>(b, a);     __syncthreads();
    pass_smem<-1, 9>(a, b);     __syncthreads();

    // spectral: fwd r2 fold + Hermitian unpack * (H+bias) * repack + inv r2 fold
    // reads A from b, writes first-inverse-pass (radix-2, s=1) output to a
    const float bs = __ldg(bias + d);
    const float2* Hf = g_Hf + (size_t)g * HFS_;
    for (int k = threadIdx.x; k < 2048; k += 1024){
        if (k == 0){
            float2 A0 = b[0],    A1 = b[4096];
            float2 A2 = b[2048], A3 = b[6144];
            float2 Z0 = cadd(A0, A1), Z4 = csub(A0, A1);
            float2 Z2 = cadd(A2, A3), Z6 = csub(A2, A3);
            // bins 0 and 8192 (both real)
            float X0 = Z0.x + Z0.y, X8 = Z0.x - Z0.y;
            float Y0 = X0 * (__ldg(&Hf[0].x)    + bs);
            float Y8 = X8 * (__ldg(&Hf[8192].x) + bs);
            float2 C0 = make_float2(0.5f*(Y0 + Y8), 0.5f*(Y0 - Y8));
            // bin 4096
            float2 X4 = make_float2(Z4.x, -Z4.y);
            float2 G4 = __ldg(&Hf[4096]); G4.x += bs;
            float2 Y4 = cmul(X4, G4);
            float2 C4 = make_float2(Y4.x, -Y4.y);
            // pair (2048, 6144)
            float2 Xk, Xm;
            float2 W2 = g_tw[2048];
            herm_unpack(Z2, Z6, W2, Xk, Xm);
            float2 Gk = __ldg(&Hf[2048]); Gk.x += bs;
            float2 Gm = __ldg(&Hf[6144]); Gm.x += bs;
            float2 C2, C6;
            herm_repack(cmul(Xk, Gk), cmul(Xm, Gm), W2, C2, C6);
            // inverse radix-2 fold: p=0 and p=2048
            a[0] = cadd(C0, C4);
            a[1] = csub(C0, C4);                          // w^0 = 1
            float2 w = g_tw[4096]; w.y = -w.y;            // e^{+i*pi/2}
            a[4096] = cadd(C2, C6);                       // sw(4096)=4096, sw(4097)=4097
            a[4097] = cmul(w, csub(C2, C6));
        } else {
            const int k2 = 4096 - k;
            const int s1 = sw(k), s2 = sw(k2);
            float2 A0 = b[s1], A1 = b[s1 + 4096];
            float2 A2 = b[s2], A3 = b[s2 + 4096];
            float2 Zk  = cadd(A0, A1);    // Z[k]
            float2 Zk4 = csub(A0, A1);    // Z[4096+k]
            float2 Zk2 = cadd(A2, A3);    // Z[4096-k]
            float2 Zm  = csub(A2, A3);    // Z[8192-k]
            float2 Wk = g_tw[k], Wk2 = g_tw[k2];
            float2 Xk, Xm, Xk2, Xk4;
            herm_unpack(Zk,  Zm,  Wk,  Xk,  Xm);    // bins k, 8192-k
            herm_unpack(Zk2, Zk4, Wk2, Xk2, Xk4);   // bins 4096-k, 4096+k
            float2 Gk  = __ldg(&Hf[k]);        Gk.x  += bs;
            float2 Gm  = __ldg(&Hf[8192 - k]); Gm.x  += bs;
            float2 Gk2 = __ldg(&Hf[k2]);       Gk2.x += bs;
            float2 Gk4 = __ldg(&Hf[4096 + k]); Gk4.x += bs;
            float2 Ck, Cm, Ck2, Ck4;
            herm_repack(cmul(Xk,  Gk),  cmul(Xm,  Gm),  Wk,  Ck,  Cm);   // C[k], C[8192-k]
            herm_repack(cmul(Xk2, Gk2), cmul(Xk4, Gk4), Wk2, Ck2, Ck4);  // C[4096-k], C[4096+k]
            // inverse radix-2 fold (s=1): p=k -> outputs 2k,2k+1 ; p=k2 -> 2k2,2k2+1
            int o1 = sw(2 * k);                           // sw(2k+1) = sw(2k)^1
            float2 wA = g_tw[2 * k];  wA.y = -wA.y;       // e^{+2*pi*i*k/8192}
            a[o1]     = cadd(Ck, Ck4);
            a[o1 ^ 1] = cmul(wA, csub(Ck, Ck4));
            int o2 = sw(2 * k2);
            float2 wB = g_tw[2 * k2]; wB.y = -wB.y;
            a[o2]     = cadd(Ck2, Cm);
            a[o2 ^ 1] = cmul(wB, csub(Ck2, Cm));
        }
    }
    __syncthreads();

    // inverse: 3 radix-8 passes + final radix-8 fused with gmem store (r<4 only)
    pass_smem<+1, 1>(a, b);     __syncthreads();
    pass_smem<+1, 4>(b, a);     __syncthreads();
    pass_smem<+1, 7>(a, b);     __syncthreads();
    float2* out2 = reinterpret_cast<float2*>(g_kvt + (size_t)c * L_);
    pass_last_inv_gmem(b, out2);
}

// -------- gate + transpose back: out(b,l,d) = x1(b,l,d) * y_t(b,d,l) -------
__global__ void gate_transpose(const float* __restrict__ x1,
                               float* __restrict__ out){
    __shared__ float tile[32][33];               // [l-local][d-local]
    const int b  = blockIdx.z;
    const int l0 = blockIdx.x * 32;
    const int d0 = blockIdx.y * 32;
    const int tx = threadIdx.x;                  // 0..7
    const int ty = threadIdx.y;                  // 0..31
    {
        float4 ya = *reinterpret_cast<const float4*>(
            g_kvt + ((size_t)b * D_ + d0 + ty) * L_ + l0 + 4 * tx);
        tile[4*tx + 0][ty] = ya.x;
        tile[4*tx + 1][ty] = ya.y;
        tile[4*tx + 2][ty] = ya.z;
        tile[4*tx + 3][ty] = ya.w;
    }
    __syncthreads();
    {
        size_t idx = ((size_t)b * L_ + (l0 + ty)) * D_ + d0 + 4 * tx;
        float4 xa = *reinterpret_cast<const float4*>(x1 + idx);
        float4 o;
        o.x = xa.x * tile[ty][4*tx + 0];
        o.y = xa.y * tile[ty][4*tx + 1];
        o.z = xa.z * tile[ty][4*tx + 2];
        o.w = xa.w * tile[ty][4*tx + 3];
        *reinterpret_cast<float4*>(out + idx) = o;
    }
}

// ---------------------------------------------------------------------------
extern "C" void kernel_launch(void* const* d_in, const int* in_sizes, int n_in,
                              void* d_out, int out_size){
    const float* x1   = (const float*)d_in[0];
    const float* x2   = (const float*)d_in[1];
    const float* v    = (const float*)d_in[2];
    const float* h    = (const float*)d_in[3];
    const float* bias = (const float*)d_in[4];
    float* out = (float*)d_out;

    const int SMEM = 2 * M_ * (int)sizeof(float2);   // 131072 B
    cudaFuncSetAttribute(hf_kernel,   cudaFuncAttributeMaxDynamicSharedMemorySize, SMEM);
    cudaFuncSetAttribute(conv_kernel, cudaFuncAttributeMaxDynamicSharedMemorySize, SMEM);

    tw_kernel<<<(M_ + 255) / 256, 256>>>();
    hf_kernel<<<G_, 1024, SMEM>>>(h);

    dim3 tgrid(L_ / 32, D_ / 32, B_);
    dim3 tblk(8, 32);
    pregate_transpose<<<tgrid, tblk>>>(x2, v);

    conv_kernel<<<B_ * D_, 1024, SMEM>>>(bias);

    gate_transpose<<<tgrid, tblk>>>(x1, out);
}